// round 8
// baseline (speedup 1.0000x reference)
#include <cuda_runtime.h>
#include <cuda_fp16.h>
#include <cstdint>

#define B_ 256
#define N_ 192
#define D_ 512
#define E_ 1024
#define H_ 512
#define K_ 58
#define M_ (B_*K_)        // 14848 real rows
#define MP_ (B_*64)       // 16384 padded rows (64 per batch, rows k>=58 stay zero)

// ---------------- scratch (static device globals; zero-init, no allocation) --
__device__ __half g_X[(size_t)MP_*1024];    // [MP,1024]: 0:512 base, 512:1024 bn(relu(h)); pad rows 0
__device__ __half g_hpre[(size_t)MP_*H_];   // [MP,512] fp16 pre-BN hidden
__device__ __half g_W1h[H_*D_];             // fp16 W1
__device__ __half g_Wcat[E_*1024];          // fp16 [W_fc | W2]
__device__ float  g_bias2[E_];              // b_fc + b2
__device__ float  g_stats[2*H_];            // col sums / sumsq
__device__ int    g_idx[B_*K_];             // selected patch indices

// ---------------- prep ---------------------------------------------------------
__global__ void prep_kernel(const float* __restrict__ Wfc, const float* __restrict__ bfc,
                            const float* __restrict__ W1,  const float* __restrict__ W2,
                            const float* __restrict__ b2)
{
    int i = blockIdx.x*blockDim.x + threadIdx.x;   // 0..1048575
    {
        int e = i >> 10, c = i & 1023;
        float v = (c < 512) ? Wfc[e*512 + c] : W2[e*512 + (c - 512)];
        g_Wcat[i] = __float2half_rn(v);
    }
    if (i < H_*D_) g_W1h[i] = __float2half_rn(W1[i]);
    if (i < E_)    g_bias2[i] = bfc[i] + b2[i];
    if (i < 2*H_)  g_stats[i] = 0.f;
}

// ---------------- top-K by rank counting (exact lax.top_k set semantics) -----
__global__ void topk_kernel(const float* __restrict__ am)
{
    __shared__ float sv[N_];
    __shared__ int cnt;
    int b = blockIdx.x, t = threadIdx.x;
    if (t == 0) cnt = 0;
    sv[t] = am[(size_t)b*((N_+1)*(N_+1)) + 1 + t];
    __syncthreads();
    float my = sv[t];
    int r = 0;
    #pragma unroll 8
    for (int i = 0; i < N_; ++i) {
        float v = sv[i];
        r += (v > my) || (v == my && i < t);
    }
    if (r < K_) {
        int p = atomicAdd(&cnt, 1);
        g_idx[b*K_ + p] = t;
    }
}

// ---------------- gather + L2 normalize + fp16 (into padded layout) -----------
__global__ void gather_kernel(const float* __restrict__ emb)
{
    int row = blockIdx.x;                 // 0..M_-1
    int b   = row / K_;
    int k   = row - b*K_;
    int p   = g_idx[row];
    const float4* src = (const float4*)(emb + (size_t)(b*N_ + p)*D_);
    int t = threadIdx.x;
    float4 v = src[t];
    float s = v.x*v.x + v.y*v.y + v.z*v.z + v.w*v.w;
    #pragma unroll
    for (int o = 16; o; o >>= 1) s += __shfl_xor_sync(0xffffffffu, s, o);
    __shared__ float sm[4];
    if ((t & 31) == 0) sm[t >> 5] = s;
    __syncthreads();
    float nrm = sqrtf(sm[0] + sm[1] + sm[2] + sm[3]) + 1e-8f;
    size_t r = (size_t)(b*64 + k);
    __half2* dst = (__half2*)(g_X + r*1024 + t*4);
    dst[0] = __floats2half2_rn(v.x/nrm, v.y/nrm);
    dst[1] = __floats2half2_rn(v.z/nrm, v.w/nrm);
}

// ---------------- fp16 tensor-core GEMM: C = A @ B^T + bias -------------------
// BM=128, BN=256, BK=64; 256 threads = 8 warps (2x4), warp tile 64x64.
// 3-stage cp.async ring (144KB dynamic smem), fragment double-buffering in ks.
// FSTAT: fp16 C store + masked BN column sums/sumsq.
// !FSTAT: BM=128 = 2 padded batches; warp-local masked max over K -> omax.
#define BMt 128
#define BNt 256
#define BK 64
#define STG 3
#define STAGE_BYTES ((BMt + BNt)*BK*2)    // 49152
#define A_BYTES (BMt*BK*2)                // 16384

__device__ __forceinline__ void cp16(uint32_t dst, const void* src) {
    asm volatile("cp.async.cg.shared.global [%0], [%1], 16;\n" :: "r"(dst), "l"(src));
}
__device__ __forceinline__ uint32_t smem_u32(const void* p) {
    uint32_t a;
    asm("{ .reg .u64 t; cvta.to.shared.u64 t, %1; cvt.u32.u64 %0, t; }" : "=r"(a) : "l"(p));
    return a;
}

template<bool FSTAT>
__global__ __launch_bounds__(256)
void gemm_tc(const __half* __restrict__ A, int lda,
             const __half* __restrict__ Bm, int ldb,
             __half* __restrict__ Ch, int ldc,
             const float* __restrict__ bias, int Kdim,
             float* __restrict__ stats, float* __restrict__ omax)
{
    extern __shared__ __half sh[];
    const int tid  = threadIdx.x;
    const int lane = tid & 31, wid = tid >> 5;
    const int wm = wid >> 2, wn = wid & 3;        // 2x4 warp grid, tile 64x64
    const int m0 = blockIdx.y*BMt, n0 = blockIdx.x*BNt;

    uint32_t sbase = smem_u32(sh);

    float acc[4][8][4];
    #pragma unroll
    for (int i = 0; i < 4; ++i)
        #pragma unroll
        for (int j = 0; j < 8; ++j)
            #pragma unroll
            for (int k = 0; k < 4; ++k) acc[i][j][k] = 0.f;

    // global->smem: 384 rows x 8 chunks(16B) / 256 thr = 12 each
    const int cr = tid >> 3;          // 0..31
    const int cc = tid & 7;           // chunk col
    const __half* Ag[4]; uint32_t oA[4];
    #pragma unroll
    for (int i = 0; i < 4; ++i) {
        int r = cr + i*32;
        Ag[i] = A + (size_t)(m0 + r)*lda + cc*8;
        oA[i] = r*128 + ((cc ^ (r & 7))*16);
    }
    const __half* Bg[8]; uint32_t oB[8];
    #pragma unroll
    for (int i = 0; i < 8; ++i) {
        int r = cr + i*32;
        Bg[i] = Bm + (size_t)(n0 + r)*ldb + cc*8;
        oB[i] = A_BYTES + r*128 + ((cc ^ (r & 7))*16);
    }

    // ldmatrix per-lane descriptors
    const int mi  = lane >> 3;
    const int lr8 = lane & 7;
    int arow[4];
    #pragma unroll
    for (int mt = 0; mt < 4; ++mt) arow[mt] = wm*64 + mt*16 + ((mi & 1) << 3) + lr8;
    const int akadd = mi >> 1;
    int brow[4];
    #pragma unroll
    for (int p = 0; p < 4; ++p) brow[p] = wn*64 + ((2*p + (mi >> 1)) << 3) + lr8;
    const int bkadd = mi & 1;

    auto issue = [&](int kt, int st) {
        uint32_t so = sbase + st*STAGE_BYTES;
        int ko = kt*BK;
        #pragma unroll
        for (int i = 0; i < 4; ++i) cp16(so + oA[i], Ag[i] + ko);
        #pragma unroll
        for (int i = 0; i < 8; ++i) cp16(so + oB[i], Bg[i] + ko);
        asm volatile("cp.async.commit_group;\n");
    };

    uint32_t a[2][4][4], bb[2][8][2];

    auto ldfrag = [&](int st, int ks, int pb) {
        uint32_t abase = sbase + st*STAGE_BYTES;
        uint32_t bbase = abase + A_BYTES;
        #pragma unroll
        for (int mt = 0; mt < 4; ++mt) {
            uint32_t ad = abase + arow[mt]*128 + (((2*ks + akadd) ^ lr8)*16);
            asm volatile("ldmatrix.sync.aligned.m8n8.x4.shared.b16 {%0,%1,%2,%3},[%4];"
                : "=r"(a[pb][mt][0]), "=r"(a[pb][mt][1]),
                  "=r"(a[pb][mt][2]), "=r"(a[pb][mt][3]) : "r"(ad));
        }
        #pragma unroll
        for (int p = 0; p < 4; ++p) {
            uint32_t bd = bbase + brow[p]*128 + (((2*ks + bkadd) ^ lr8)*16);
            asm volatile("ldmatrix.sync.aligned.m8n8.x4.shared.b16 {%0,%1,%2,%3},[%4];"
                : "=r"(bb[pb][2*p][0]), "=r"(bb[pb][2*p][1]),
                  "=r"(bb[pb][2*p+1][0]), "=r"(bb[pb][2*p+1][1]) : "r"(bd));
        }
    };

    auto mmas = [&](int pb) {
        #pragma unroll
        for (int mt = 0; mt < 4; ++mt)
            #pragma unroll
            for (int nt = 0; nt < 8; ++nt)
                asm volatile(
                    "mma.sync.aligned.m16n8k16.row.col.f32.f16.f16.f32 "
                    "{%0,%1,%2,%3},{%4,%5,%6,%7},{%8,%9},{%0,%1,%2,%3};\n"
                    : "+f"(acc[mt][nt][0]), "+f"(acc[mt][nt][1]),
                      "+f"(acc[mt][nt][2]), "+f"(acc[mt][nt][3])
                    : "r"(a[pb][mt][0]), "r"(a[pb][mt][1]),
                      "r"(a[pb][mt][2]), "r"(a[pb][mt][3]),
                      "r"(bb[pb][nt][0]), "r"(bb[pb][nt][1]));
    };

    const int ntile = Kdim / BK;
    issue(0, 0);
    issue(1, 1);
    for (int t = 0; t < ntile; ++t) {
        if (t + 1 < ntile) asm volatile("cp.async.wait_group 1;\n" ::: "memory");
        else               asm volatile("cp.async.wait_group 0;\n" ::: "memory");
        __syncthreads();
        int st = t % STG;
        // ks-loop with fragment double-buffering: prefetch ks+1 during mma(ks)
        ldfrag(st, 0, 0);
        #pragma unroll
        for (int ks = 0; ks < 4; ++ks) {
            int cur = ks & 1;
            if (ks < 3) ldfrag(st, ks + 1, cur ^ 1);
            mmas(cur);
        }
        if (t + 2 < ntile) issue(t + 2, (t + 2) % STG);
    }

    const int g = lane >> 2, q = lane & 3;

    if (FSTAT) {
        // fp16 C store (all rows incl. padding) + masked BN stats from fp32 accs.
        float sum[16], sq[16];
        #pragma unroll
        for (int i = 0; i < 16; ++i) { sum[i] = 0.f; sq[i] = 0.f; }
        #pragma unroll
        for (int mt = 0; mt < 4; ++mt) {
            int rr = wm*64 + mt*16 + g;
            bool ok0 = (rr & 63) < K_;
            bool ok1 = ((rr + 8) & 63) < K_;
            #pragma unroll
            for (int nt = 0; nt < 8; ++nt) {
                int c = n0 + wn*64 + nt*8 + q*2;
                float b0 = bias[c], b1 = bias[c+1];
                float v00 = acc[mt][nt][0] + b0, v01 = acc[mt][nt][1] + b1;
                float v10 = acc[mt][nt][2] + b0, v11 = acc[mt][nt][3] + b1;
                int r = m0 + rr;
                *(__half2*)&Ch[(size_t)r*ldc + c]     = __floats2half2_rn(v00, v01);
                *(__half2*)&Ch[(size_t)(r+8)*ldc + c] = __floats2half2_rn(v10, v11);
                if (ok0) { sum[nt*2]   += v00; sq[nt*2]   += v00*v00;
                           sum[nt*2+1] += v01; sq[nt*2+1] += v01*v01; }
                if (ok1) { sum[nt*2]   += v10; sq[nt*2]   += v10*v10;
                           sum[nt*2+1] += v11; sq[nt*2+1] += v11*v11; }
            }
        }
        #pragma unroll
        for (int off = 4; off < 32; off <<= 1) {
            #pragma unroll
            for (int i = 0; i < 16; ++i) {
                sum[i] += __shfl_xor_sync(0xffffffffu, sum[i], off);
                sq[i]  += __shfl_xor_sync(0xffffffffu, sq[i],  off);
            }
        }
        if (lane < 4) {
            #pragma unroll
            for (int nt = 0; nt < 8; ++nt) {
                #pragma unroll
                for (int j = 0; j < 2; ++j) {
                    int c = n0 + wn*64 + nt*8 + lane*2 + j;
                    atomicAdd(&stats[c],      sum[nt*2+j]);
                    atomicAdd(&stats[H_ + c], sq[nt*2+j]);
                }
            }
        }
    } else {
        // 2 batches per CTA; warp row wm owns batch 2*by+wm (rows wm*64..+63).
        float mx[16];
        #pragma unroll
        for (int i = 0; i < 16; ++i) mx[i] = -3.4e38f;
        #pragma unroll
        for (int mt = 0; mt < 4; ++mt) {
            int k0 = mt*16 + g;               // row within batch
            bool ok0 = k0 < K_, ok1 = (k0 + 8) < K_;
            #pragma unroll
            for (int nt = 0; nt < 8; ++nt) {
                int c = n0 + wn*64 + nt*8 + q*2;
                float b0 = bias[c], b1 = bias[c+1];
                if (ok0) { mx[nt*2]   = fmaxf(mx[nt*2],   acc[mt][nt][0] + b0);
                           mx[nt*2+1] = fmaxf(mx[nt*2+1], acc[mt][nt][1] + b1); }
                if (ok1) { mx[nt*2]   = fmaxf(mx[nt*2],   acc[mt][nt][2] + b0);
                           mx[nt*2+1] = fmaxf(mx[nt*2+1], acc[mt][nt][3] + b1); }
            }
        }
        #pragma unroll
        for (int off = 4; off < 32; off <<= 1)
            #pragma unroll
            for (int i = 0; i < 16; ++i)
                mx[i] = fmaxf(mx[i], __shfl_xor_sync(0xffffffffu, mx[i], off));
        if (lane < 4) {
            int b = blockIdx.y*2 + wm;
            #pragma unroll
            for (int nt = 0; nt < 8; ++nt) {
                int c = n0 + wn*64 + nt*8 + lane*2;
                *(float2*)&omax[(size_t)b*E_ + c] = make_float2(mx[nt*2], mx[nt*2+1]);
            }
        }
    }
}

// ---------------- BN apply + ReLU + fp16 into X[:,512:] (real rows only) ------
__global__ void bnapply_kernel(const float* __restrict__ gamma, const float* __restrict__ beta)
{
    int i = blockIdx.x*256 + threadIdx.x;    // 0..M_*H_/2-1
    int row = i >> 8;                        // real row 0..14847
    int cp = (i & 255)*2;
    int b = row / K_;
    int k = row - b*K_;
    size_t r = (size_t)(b*64 + k);
    __half2 x2 = *(const __half2*)&g_hpre[r*H_ + cp];
    const float invM = 1.f / (float)M_;
    float y0, y1;
    {
        float mu  = g_stats[cp] * invM;
        float var = g_stats[H_ + cp] * invM - mu*mu;
        y0 = fmaxf((__low2float(x2) - mu) * rsqrtf(var + 1e-5f) * gamma[cp] + beta[cp], 0.f);
    }
    {
        float mu  = g_stats[cp+1] * invM;
        float var = g_stats[H_ + cp+1] * invM - mu*mu;
        y1 = fmaxf((__high2float(x2) - mu) * rsqrtf(var + 1e-5f) * gamma[cp+1] + beta[cp+1], 0.f);
    }
    *(__half2*)&g_X[r*1024 + 512 + cp] = __floats2half2_rn(y0, y1);
}

// ---------------- launch ------------------------------------------------------
extern "C" void kernel_launch(void* const* d_in, const int* in_sizes, int n_in,
                              void* d_out, int out_size)
{
    const float* emb   = (const float*)d_in[0];
    const float* am    = (const float*)d_in[1];
    const float* Wfc   = (const float*)d_in[2];
    const float* bfc   = (const float*)d_in[3];
    const float* W1    = (const float*)d_in[4];
    const float* b1    = (const float*)d_in[5];
    const float* gamma = (const float*)d_in[6];
    const float* beta  = (const float*)d_in[7];
    const float* W2    = (const float*)d_in[8];
    const float* b2    = (const float*)d_in[9];
    float* out = (float*)d_out;

    void *pX, *pW1h, *pWcat, *pH, *pB2, *pSt;
    cudaGetSymbolAddress(&pX,    g_X);
    cudaGetSymbolAddress(&pW1h,  g_W1h);
    cudaGetSymbolAddress(&pWcat, g_Wcat);
    cudaGetSymbolAddress(&pH,    g_hpre);
    cudaGetSymbolAddress(&pB2,   g_bias2);
    cudaGetSymbolAddress(&pSt,   g_stats);

    const int SMEM = STG*STAGE_BYTES;   // 147456
    cudaFuncSetAttribute(gemm_tc<true>,  cudaFuncAttributeMaxDynamicSharedMemorySize, SMEM);
    cudaFuncSetAttribute(gemm_tc<false>, cudaFuncAttributeMaxDynamicSharedMemorySize, SMEM);

    prep_kernel<<<4096, 256>>>(Wfc, bfc, W1, W2, b2);
    topk_kernel<<<B_, N_>>>(am);
    gather_kernel<<<M_, 128>>>(emb);
    // GEMM1: hpre(fp16) = base @ W1^T + b1, fused BN stats (K=512 -> 8 tiles)
    gemm_tc<true><<<dim3(H_/BNt, MP_/BMt), 256, SMEM>>>(
        (const __half*)pX, 1024, (const __half*)pW1h, D_,
        (__half*)pH, H_, b1, D_, (float*)pSt, nullptr);
    bnapply_kernel<<<(M_*H_/2)/256, 256>>>(gamma, beta);
    // GEMM2: out[b,:] = max_k( X @ [Wfc|W2]^T + (b_fc+b2) ), warp-local max epilogue
    gemm_tc<false><<<dim3(E_/BNt, MP_/BMt), 256, SMEM>>>(
        (const __half*)pX, 1024, (const __half*)pWcat, 1024,
        nullptr, 0, (const float*)pB2, 1024, nullptr, out);
}

// round 9
// speedup vs baseline: 1.0231x; 1.0231x over previous
#include <cuda_runtime.h>
#include <cuda_fp16.h>
#include <cstdint>

#define B_ 256
#define N_ 192
#define D_ 512
#define E_ 1024
#define H_ 512
#define K_ 58
#define M_ (B_*K_)        // 14848 real rows
#define MP_ (B_*64)       // 16384 padded rows (64 per batch, rows k>=58 stay zero)

// ---------------- scratch (static device globals; zero-init, no allocation) --
__device__ __half g_X[(size_t)MP_*1024];    // [MP,1024]: 0:512 base, 512:1024 bn(relu(h)); pad rows 0
__device__ __half g_hpre[(size_t)MP_*H_];   // [MP,512] fp16 pre-BN hidden
__device__ __half g_W1h[H_*D_];             // fp16 W1
__device__ __half g_Wcat[E_*1024];          // fp16 [W_fc | W2]
__device__ float  g_bias2[E_];              // b_fc + b2
__device__ float  g_stats[2*H_];            // col sums / sumsq
__device__ int    g_idx[B_*K_];             // selected patch indices

// ---------------- prep ---------------------------------------------------------
__global__ void prep_kernel(const float* __restrict__ Wfc, const float* __restrict__ bfc,
                            const float* __restrict__ W1,  const float* __restrict__ W2,
                            const float* __restrict__ b2)
{
    int i = blockIdx.x*blockDim.x + threadIdx.x;   // 0..1048575
    {
        int e = i >> 10, c = i & 1023;
        float v = (c < 512) ? Wfc[e*512 + c] : W2[e*512 + (c - 512)];
        g_Wcat[i] = __float2half_rn(v);
    }
    if (i < H_*D_) g_W1h[i] = __float2half_rn(W1[i]);
    if (i < E_)    g_bias2[i] = bfc[i] + b2[i];
    if (i < 2*H_)  g_stats[i] = 0.f;
}

// ---------------- top-K by rank counting (exact lax.top_k set semantics) -----
__global__ void topk_kernel(const float* __restrict__ am)
{
    __shared__ float sv[N_];
    __shared__ int cnt;
    int b = blockIdx.x, t = threadIdx.x;
    if (t == 0) cnt = 0;
    sv[t] = am[(size_t)b*((N_+1)*(N_+1)) + 1 + t];
    __syncthreads();
    float my = sv[t];
    int r = 0;
    #pragma unroll 8
    for (int i = 0; i < N_; ++i) {
        float v = sv[i];
        r += (v > my) || (v == my && i < t);
    }
    if (r < K_) {
        int p = atomicAdd(&cnt, 1);
        g_idx[b*K_ + p] = t;
    }
}

// ---------------- gather + L2 normalize + fp16 (into padded layout) -----------
__global__ void gather_kernel(const float* __restrict__ emb)
{
    int row = blockIdx.x;                 // 0..M_-1
    int b   = row / K_;
    int k   = row - b*K_;
    int p   = g_idx[row];
    const float4* src = (const float4*)(emb + (size_t)(b*N_ + p)*D_);
    int t = threadIdx.x;
    float4 v = src[t];
    float s = v.x*v.x + v.y*v.y + v.z*v.z + v.w*v.w;
    #pragma unroll
    for (int o = 16; o; o >>= 1) s += __shfl_xor_sync(0xffffffffu, s, o);
    __shared__ float sm[4];
    if ((t & 31) == 0) sm[t >> 5] = s;
    __syncthreads();
    float nrm = sqrtf(sm[0] + sm[1] + sm[2] + sm[3]) + 1e-8f;
    size_t r = (size_t)(b*64 + k);
    __half2* dst = (__half2*)(g_X + r*1024 + t*4);
    dst[0] = __floats2half2_rn(v.x/nrm, v.y/nrm);
    dst[1] = __floats2half2_rn(v.z/nrm, v.w/nrm);
}

// ---------------- fp16 tensor-core GEMM: C = A @ B^T + bias -------------------
// BM=128, BN=128, BK=32; 128 threads = 4 warps (2x2), warp tile 64x64.
// 5-stage cp.async ring (80KB dynamic smem) -> 2 CTAs/SM; 3 tiles in flight.
// smem rows are 64B (4x16B chunks); swizzle phys_chunk = c ^ ((r>>1)&3)
// gives each ldmatrix 8 distinct 16B slots (conflict-free).
// FSTAT: fp16 C store + masked BN column sums/sumsq.
// !FSTAT: BM=128 = 2 padded batches; warp-local masked max over K -> omax.
#define BMt 128
#define BN 128
#define BK 32
#define STG 5
#define STAGE_BYTES ((BMt + BN)*BK*2)     // 16384
#define A_BYTES (BMt*BK*2)                // 8192

__device__ __forceinline__ void cp16(uint32_t dst, const void* src) {
    asm volatile("cp.async.cg.shared.global [%0], [%1], 16;\n" :: "r"(dst), "l"(src));
}
__device__ __forceinline__ uint32_t smem_u32(const void* p) {
    uint32_t a;
    asm("{ .reg .u64 t; cvta.to.shared.u64 t, %1; cvt.u32.u64 %0, t; }" : "=r"(a) : "l"(p));
    return a;
}

template<bool FSTAT>
__global__ __launch_bounds__(128)
void gemm_tc(const __half* __restrict__ A, int lda,
             const __half* __restrict__ Bm, int ldb,
             __half* __restrict__ Ch, int ldc,
             const float* __restrict__ bias, int Kdim,
             float* __restrict__ stats, float* __restrict__ omax)
{
    extern __shared__ __half sh[];
    const int tid  = threadIdx.x;
    const int lane = tid & 31, wid = tid >> 5;
    const int wm = wid >> 1, wn = wid & 1;        // 2x2 warp grid, tile 64x64
    const int m0 = blockIdx.y*BMt, n0 = blockIdx.x*BN;

    uint32_t sbase = smem_u32(sh);

    float acc[4][8][4];
    #pragma unroll
    for (int i = 0; i < 4; ++i)
        #pragma unroll
        for (int j = 0; j < 8; ++j)
            #pragma unroll
            for (int k = 0; k < 4; ++k) acc[i][j][k] = 0.f;

    // global->smem: 256 rows x 4 chunks(16B) = 1024 chunks / 128 thr = 8 each
    const int cr = tid >> 2;          // 0..31
    const int cc = tid & 3;           // chunk col 0..3
    const __half* Ag[4]; uint32_t oA[4];
    #pragma unroll
    for (int i = 0; i < 4; ++i) {
        int r = cr + i*32;
        Ag[i] = A + (size_t)(m0 + r)*lda + cc*8;
        oA[i] = r*64 + ((cc ^ ((r >> 1) & 3))*16);
    }
    const __half* Bg[4]; uint32_t oB[4];
    #pragma unroll
    for (int i = 0; i < 4; ++i) {
        int r = cr + i*32;
        Bg[i] = Bm + (size_t)(n0 + r)*ldb + cc*8;
        oB[i] = A_BYTES + r*64 + ((cc ^ ((r >> 1) & 3))*16);
    }

    // ldmatrix per-lane descriptors
    const int mi  = lane >> 3;
    const int lr8 = lane & 7;
    int arow[4];
    #pragma unroll
    for (int mt = 0; mt < 4; ++mt) arow[mt] = wm*64 + mt*16 + ((mi & 1) << 3) + lr8;
    const int akadd = mi >> 1;
    int brow[4];
    #pragma unroll
    for (int p = 0; p < 4; ++p) brow[p] = wn*64 + ((2*p + (mi >> 1)) << 3) + lr8;
    const int bkadd = mi & 1;

    auto issue = [&](int kt, int st) {
        uint32_t so = sbase + st*STAGE_BYTES;
        int ko = kt*BK;
        #pragma unroll
        for (int i = 0; i < 4; ++i) cp16(so + oA[i], Ag[i] + ko);
        #pragma unroll
        for (int i = 0; i < 4; ++i) cp16(so + oB[i], Bg[i] + ko);
        asm volatile("cp.async.commit_group;\n");
    };

    auto compute = [&](int st) {
        uint32_t abase = sbase + st*STAGE_BYTES;
        uint32_t bbase = abase + A_BYTES;
        #pragma unroll
        for (int ks = 0; ks < 2; ++ks) {
            uint32_t a[4][4], bb[8][2];
            #pragma unroll
            for (int mt = 0; mt < 4; ++mt) {
                int rr = arow[mt];
                uint32_t ad = abase + rr*64 + (((2*ks + akadd) ^ ((rr >> 1) & 3))*16);
                asm volatile("ldmatrix.sync.aligned.m8n8.x4.shared.b16 {%0,%1,%2,%3},[%4];"
                    : "=r"(a[mt][0]), "=r"(a[mt][1]), "=r"(a[mt][2]), "=r"(a[mt][3]) : "r"(ad));
            }
            #pragma unroll
            for (int p = 0; p < 4; ++p) {
                int rr = brow[p];
                uint32_t bd = bbase + rr*64 + (((2*ks + bkadd) ^ ((rr >> 1) & 3))*16);
                asm volatile("ldmatrix.sync.aligned.m8n8.x4.shared.b16 {%0,%1,%2,%3},[%4];"
                    : "=r"(bb[2*p][0]), "=r"(bb[2*p][1]),
                      "=r"(bb[2*p+1][0]), "=r"(bb[2*p+1][1]) : "r"(bd));
            }
            #pragma unroll
            for (int mt = 0; mt < 4; ++mt)
                #pragma unroll
                for (int nt = 0; nt < 8; ++nt)
                    asm volatile(
                        "mma.sync.aligned.m16n8k16.row.col.f32.f16.f16.f32 "
                        "{%0,%1,%2,%3},{%4,%5,%6,%7},{%8,%9},{%0,%1,%2,%3};\n"
                        : "+f"(acc[mt][nt][0]), "+f"(acc[mt][nt][1]),
                          "+f"(acc[mt][nt][2]), "+f"(acc[mt][nt][3])
                        : "r"(a[mt][0]), "r"(a[mt][1]), "r"(a[mt][2]), "r"(a[mt][3]),
                          "r"(bb[nt][0]), "r"(bb[nt][1]));
        }
    };

    const int ntile = Kdim / BK;
    issue(0, 0);
    issue(1, 1);
    issue(2, 2);
    issue(3, 3);
    for (int t = 0; t < ntile; ++t) {
        int rem = ntile - 1 - t;
        if      (rem >= 3) asm volatile("cp.async.wait_group 3;\n" ::: "memory");
        else if (rem == 2) asm volatile("cp.async.wait_group 2;\n" ::: "memory");
        else if (rem == 1) asm volatile("cp.async.wait_group 1;\n" ::: "memory");
        else               asm volatile("cp.async.wait_group 0;\n" ::: "memory");
        __syncthreads();
        compute(t % STG);
        if (t + 4 < ntile) issue(t + 4, (t + 4) % STG);
    }

    const int g = lane >> 2, q = lane & 3;

    if (FSTAT) {
        // fp16 C store (all rows incl. padding) + masked BN stats from fp32 accs.
        float sum[16], sq[16];
        #pragma unroll
        for (int i = 0; i < 16; ++i) { sum[i] = 0.f; sq[i] = 0.f; }
        #pragma unroll
        for (int mt = 0; mt < 4; ++mt) {
            int rr = wm*64 + mt*16 + g;
            bool ok0 = (rr & 63) < K_;
            bool ok1 = ((rr + 8) & 63) < K_;
            #pragma unroll
            for (int nt = 0; nt < 8; ++nt) {
                int c = n0 + wn*64 + nt*8 + q*2;
                float b0 = bias[c], b1 = bias[c+1];
                float v00 = acc[mt][nt][0] + b0, v01 = acc[mt][nt][1] + b1;
                float v10 = acc[mt][nt][2] + b0, v11 = acc[mt][nt][3] + b1;
                int r = m0 + rr;
                *(__half2*)&Ch[(size_t)r*ldc + c]     = __floats2half2_rn(v00, v01);
                *(__half2*)&Ch[(size_t)(r+8)*ldc + c] = __floats2half2_rn(v10, v11);
                if (ok0) { sum[nt*2]   += v00; sq[nt*2]   += v00*v00;
                           sum[nt*2+1] += v01; sq[nt*2+1] += v01*v01; }
                if (ok1) { sum[nt*2]   += v10; sq[nt*2]   += v10*v10;
                           sum[nt*2+1] += v11; sq[nt*2+1] += v11*v11; }
            }
        }
        #pragma unroll
        for (int off = 4; off < 32; off <<= 1) {
            #pragma unroll
            for (int i = 0; i < 16; ++i) {
                sum[i] += __shfl_xor_sync(0xffffffffu, sum[i], off);
                sq[i]  += __shfl_xor_sync(0xffffffffu, sq[i],  off);
            }
        }
        if (lane < 4) {
            #pragma unroll
            for (int nt = 0; nt < 8; ++nt) {
                #pragma unroll
                for (int j = 0; j < 2; ++j) {
                    int c = n0 + wn*64 + nt*8 + lane*2 + j;
                    atomicAdd(&stats[c],      sum[nt*2+j]);
                    atomicAdd(&stats[H_ + c], sq[nt*2+j]);
                }
            }
        }
    } else {
        // 2 batches per CTA; warp row wm owns batch 2*by+wm (rows wm*64..+63).
        float mx[16];
        #pragma unroll
        for (int i = 0; i < 16; ++i) mx[i] = -3.4e38f;
        #pragma unroll
        for (int mt = 0; mt < 4; ++mt) {
            int k0 = mt*16 + g;               // row within batch
            bool ok0 = k0 < K_, ok1 = (k0 + 8) < K_;
            #pragma unroll
            for (int nt = 0; nt < 8; ++nt) {
                int c = n0 + wn*64 + nt*8 + q*2;
                float b0 = bias[c], b1 = bias[c+1];
                if (ok0) { mx[nt*2]   = fmaxf(mx[nt*2],   acc[mt][nt][0] + b0);
                           mx[nt*2+1] = fmaxf(mx[nt*2+1], acc[mt][nt][1] + b1); }
                if (ok1) { mx[nt*2]   = fmaxf(mx[nt*2],   acc[mt][nt][2] + b0);
                           mx[nt*2+1] = fmaxf(mx[nt*2+1], acc[mt][nt][3] + b1); }
            }
        }
        #pragma unroll
        for (int off = 4; off < 32; off <<= 1)
            #pragma unroll
            for (int i = 0; i < 16; ++i)
                mx[i] = fmaxf(mx[i], __shfl_xor_sync(0xffffffffu, mx[i], off));
        if (lane < 4) {
            int b = blockIdx.y*2 + wm;
            #pragma unroll
            for (int nt = 0; nt < 8; ++nt) {
                int c = n0 + wn*64 + nt*8 + lane*2;
                *(float2*)&omax[(size_t)b*E_ + c] = make_float2(mx[nt*2], mx[nt*2+1]);
            }
        }
    }
}

// ---------------- BN apply + ReLU + fp16 into X[:,512:] (real rows only) ------
__global__ void bnapply_kernel(const float* __restrict__ gamma, const float* __restrict__ beta)
{
    int i = blockIdx.x*256 + threadIdx.x;    // 0..M_*H_/2-1
    int row = i >> 8;                        // real row 0..14847
    int cp = (i & 255)*2;
    int b = row / K_;
    int k = row - b*K_;
    size_t r = (size_t)(b*64 + k);
    __half2 x2 = *(const __half2*)&g_hpre[r*H_ + cp];
    const float invM = 1.f / (float)M_;
    float y0, y1;
    {
        float mu  = g_stats[cp] * invM;
        float var = g_stats[H_ + cp] * invM - mu*mu;
        y0 = fmaxf((__low2float(x2) - mu) * rsqrtf(var + 1e-5f) * gamma[cp] + beta[cp], 0.f);
    }
    {
        float mu  = g_stats[cp+1] * invM;
        float var = g_stats[H_ + cp+1] * invM - mu*mu;
        y1 = fmaxf((__high2float(x2) - mu) * rsqrtf(var + 1e-5f) * gamma[cp+1] + beta[cp+1], 0.f);
    }
    *(__half2*)&g_X[r*1024 + 512 + cp] = __floats2half2_rn(y0, y1);
}

// ---------------- launch ------------------------------------------------------
extern "C" void kernel_launch(void* const* d_in, const int* in_sizes, int n_in,
                              void* d_out, int out_size)
{
    const float* emb   = (const float*)d_in[0];
    const float* am    = (const float*)d_in[1];
    const float* Wfc   = (const float*)d_in[2];
    const float* bfc   = (const float*)d_in[3];
    const float* W1    = (const float*)d_in[4];
    const float* b1    = (const float*)d_in[5];
    const float* gamma = (const float*)d_in[6];
    const float* beta  = (const float*)d_in[7];
    const float* W2    = (const float*)d_in[8];
    const float* b2    = (const float*)d_in[9];
    float* out = (float*)d_out;

    void *pX, *pW1h, *pWcat, *pH, *pB2, *pSt;
    cudaGetSymbolAddress(&pX,    g_X);
    cudaGetSymbolAddress(&pW1h,  g_W1h);
    cudaGetSymbolAddress(&pWcat, g_Wcat);
    cudaGetSymbolAddress(&pH,    g_hpre);
    cudaGetSymbolAddress(&pB2,   g_bias2);
    cudaGetSymbolAddress(&pSt,   g_stats);

    const int SMEM = STG*STAGE_BYTES;   // 81920
    cudaFuncSetAttribute(gemm_tc<true>,  cudaFuncAttributeMaxDynamicSharedMemorySize, SMEM);
    cudaFuncSetAttribute(gemm_tc<false>, cudaFuncAttributeMaxDynamicSharedMemorySize, SMEM);

    prep_kernel<<<4096, 256>>>(Wfc, bfc, W1, W2, b2);
    topk_kernel<<<B_, N_>>>(am);
    gather_kernel<<<M_, 128>>>(emb);
    // GEMM1: hpre(fp16) = base @ W1^T + b1, fused BN stats (K=512 -> 16 tiles)
    gemm_tc<true><<<dim3(H_/BN, MP_/BMt), 128, SMEM>>>(
        (const __half*)pX, 1024, (const __half*)pW1h, D_,
        (__half*)pH, H_, b1, D_, (float*)pSt, nullptr);
    bnapply_kernel<<<(M_*H_/2)/256, 256>>>(gamma, beta);
    // GEMM2: out[b,:] = max_k( X @ [Wfc|W2]^T + (b_fc+b2) ), warp-local max epilogue
    gemm_tc<false><<<dim3(E_/BN, MP_/BMt), 128, SMEM>>>(
        (const __half*)pX, 1024, (const __half*)pWcat, 1024,
        nullptr, 0, (const float*)pB2, 1024, nullptr, out);
}

// round 10
// speedup vs baseline: 1.0864x; 1.0618x over previous
#include <cuda_runtime.h>
#include <cuda_fp16.h>
#include <cstdint>

#define B_ 256
#define N_ 192
#define D_ 512
#define E_ 1024
#define H_ 512
#define K_ 58
#define M_ (B_*K_)        // 14848 real rows
#define MP_ (B_*64)       // 16384 padded rows (64 per batch, rows k>=58 stay zero)

// ---------------- scratch (static device globals; zero-init, no allocation) --
__device__ __half g_X[(size_t)MP_*1024];    // [MP,1024]: 0:512 base, 512:1024 bn(relu(h)); pad rows 0
__device__ __half g_hpre[(size_t)MP_*H_];   // [MP,512] fp16 pre-BN hidden
__device__ __half g_W1h[H_*D_];             // fp16 W1
__device__ __half g_Wcat[E_*1024];          // fp16 [W_fc | W2]
__device__ float  g_bias2[E_];              // b_fc + b2
__device__ float  g_stats[2*H_];            // col sums / sumsq
__device__ int    g_idx[B_*K_];             // selected patch indices

// ---------------- prep ---------------------------------------------------------
__global__ void prep_kernel(const float* __restrict__ Wfc, const float* __restrict__ bfc,
                            const float* __restrict__ W1,  const float* __restrict__ W2,
                            const float* __restrict__ b2)
{
    int i = blockIdx.x*blockDim.x + threadIdx.x;   // 0..1048575
    {
        int e = i >> 10, c = i & 1023;
        float v = (c < 512) ? Wfc[e*512 + c] : W2[e*512 + (c - 512)];
        g_Wcat[i] = __float2half_rn(v);
    }
    if (i < H_*D_) g_W1h[i] = __float2half_rn(W1[i]);
    if (i < E_)    g_bias2[i] = bfc[i] + b2[i];
    if (i < 2*H_)  g_stats[i] = 0.f;
}

// ---------------- top-K by rank counting (exact lax.top_k set semantics) -----
__global__ void topk_kernel(const float* __restrict__ am)
{
    __shared__ float sv[N_];
    __shared__ int cnt;
    int b = blockIdx.x, t = threadIdx.x;
    if (t == 0) cnt = 0;
    sv[t] = am[(size_t)b*((N_+1)*(N_+1)) + 1 + t];
    __syncthreads();
    float my = sv[t];
    int r = 0;
    #pragma unroll 8
    for (int i = 0; i < N_; ++i) {
        float v = sv[i];
        r += (v > my) || (v == my && i < t);
    }
    if (r < K_) {
        int p = atomicAdd(&cnt, 1);
        g_idx[b*K_ + p] = t;
    }
}

// ---------------- gather + L2 normalize + fp16 (into padded layout) -----------
__global__ void gather_kernel(const float* __restrict__ emb)
{
    int row = blockIdx.x;                 // 0..M_-1
    int b   = row / K_;
    int k   = row - b*K_;
    int p   = g_idx[row];
    const float4* src = (const float4*)(emb + (size_t)(b*N_ + p)*D_);
    int t = threadIdx.x;
    float4 v = src[t];
    float s = v.x*v.x + v.y*v.y + v.z*v.z + v.w*v.w;
    #pragma unroll
    for (int o = 16; o; o >>= 1) s += __shfl_xor_sync(0xffffffffu, s, o);
    __shared__ float sm[4];
    if ((t & 31) == 0) sm[t >> 5] = s;
    __syncthreads();
    float nrm = sqrtf(sm[0] + sm[1] + sm[2] + sm[3]) + 1e-8f;
    size_t r = (size_t)(b*64 + k);
    __half2* dst = (__half2*)(g_X + r*1024 + t*4);
    dst[0] = __floats2half2_rn(v.x/nrm, v.y/nrm);
    dst[1] = __floats2half2_rn(v.z/nrm, v.w/nrm);
}

// ---------------- fp16 tensor-core GEMM: C = A @ B^T + bias -------------------
// BM=128, BN=128, BK=64; 128 threads = 4 warps (2x2), warp tile 64x64.
// STGt-stage cp.async ring; MINB = min blocks/SM (reg cap).
// GEMM1: STGt=2, MINB=3 (64KB smem, 3 CTAs/SM, 1.15 waves).
// GEMM2: STGt=3, MINB=2 (96KB smem, 2 CTAs/SM) == R7-exact.
// FSTAT: fp16 C store (real rows only) + masked BN column sums/sumsq.
// !FSTAT: BM=128 = 2 padded batches; warp-local masked max over K -> omax.
#define BMt 128
#define BN 128
#define BK 64
#define STAGE_BYTES ((BMt + BN)*BK*2)     // 32768
#define A_BYTES (BMt*BK*2)                // 16384

__device__ __forceinline__ void cp16(uint32_t dst, const void* src) {
    asm volatile("cp.async.cg.shared.global [%0], [%1], 16;\n" :: "r"(dst), "l"(src));
}
__device__ __forceinline__ uint32_t smem_u32(const void* p) {
    uint32_t a;
    asm("{ .reg .u64 t; cvta.to.shared.u64 t, %1; cvt.u32.u64 %0, t; }" : "=r"(a) : "l"(p));
    return a;
}

template<bool FSTAT, int STGt, int MINB>
__global__ __launch_bounds__(128, MINB)
void gemm_tc(const __half* __restrict__ A, int lda,
             const __half* __restrict__ Bm, int ldb,
             __half* __restrict__ Ch, int ldc,
             const float* __restrict__ bias, int Kdim,
             float* __restrict__ stats, float* __restrict__ omax)
{
    extern __shared__ __half sh[];
    const int tid  = threadIdx.x;
    const int lane = tid & 31, wid = tid >> 5;
    const int wm = wid >> 1, wn = wid & 1;        // 2x2 warp grid, tile 64x64
    const int m0 = blockIdx.y*BMt, n0 = blockIdx.x*BN;

    uint32_t sbase = smem_u32(sh);

    float acc[4][8][4];
    #pragma unroll
    for (int i = 0; i < 4; ++i)
        #pragma unroll
        for (int j = 0; j < 8; ++j)
            #pragma unroll
            for (int k = 0; k < 4; ++k) acc[i][j][k] = 0.f;

    // global->smem: 256 rows x 8 chunks(16B) = 2048 chunks / 128 thr = 16 each
    const int cr = tid >> 3;          // 0..15
    const int cc = tid & 7;           // chunk col
    const __half* Ag[8]; uint32_t oA[8];
    #pragma unroll
    for (int i = 0; i < 8; ++i) {
        int r = cr + i*16;
        Ag[i] = A + (size_t)(m0 + r)*lda + cc*8;
        oA[i] = r*128 + ((cc ^ (r & 7))*16);
    }
    const __half* Bg[8]; uint32_t oB[8];
    #pragma unroll
    for (int i = 0; i < 8; ++i) {
        int r = cr + i*16;
        Bg[i] = Bm + (size_t)(n0 + r)*ldb + cc*8;
        oB[i] = A_BYTES + r*128 + ((cc ^ (r & 7))*16);
    }

    // ldmatrix per-lane descriptors
    const int mi  = lane >> 3;
    const int lr8 = lane & 7;
    int arow[4];
    #pragma unroll
    for (int mt = 0; mt < 4; ++mt) arow[mt] = wm*64 + mt*16 + ((mi & 1) << 3) + lr8;
    const int akadd = mi >> 1;
    int brow[4];
    #pragma unroll
    for (int p = 0; p < 4; ++p) brow[p] = wn*64 + ((2*p + (mi >> 1)) << 3) + lr8;
    const int bkadd = mi & 1;

    auto issue = [&](int kt, int st) {
        uint32_t so = sbase + st*STAGE_BYTES;
        int ko = kt*BK;
        #pragma unroll
        for (int i = 0; i < 8; ++i) cp16(so + oA[i], Ag[i] + ko);
        #pragma unroll
        for (int i = 0; i < 8; ++i) cp16(so + oB[i], Bg[i] + ko);
        asm volatile("cp.async.commit_group;\n");
    };

    auto compute = [&](int st) {
        uint32_t abase = sbase + st*STAGE_BYTES;
        uint32_t bbase = abase + A_BYTES;
        #pragma unroll
        for (int ks = 0; ks < 4; ++ks) {
            uint32_t a[4][4], bb[8][2];
            #pragma unroll
            for (int mt = 0; mt < 4; ++mt) {
                uint32_t ad = abase + arow[mt]*128 + (((2*ks + akadd) ^ lr8)*16);
                asm volatile("ldmatrix.sync.aligned.m8n8.x4.shared.b16 {%0,%1,%2,%3},[%4];"
                    : "=r"(a[mt][0]), "=r"(a[mt][1]), "=r"(a[mt][2]), "=r"(a[mt][3]) : "r"(ad));
            }
            #pragma unroll
            for (int p = 0; p < 4; ++p) {
                uint32_t bd = bbase + brow[p]*128 + (((2*ks + bkadd) ^ lr8)*16);
                asm volatile("ldmatrix.sync.aligned.m8n8.x4.shared.b16 {%0,%1,%2,%3},[%4];"
                    : "=r"(bb[2*p][0]), "=r"(bb[2*p][1]),
                      "=r"(bb[2*p+1][0]), "=r"(bb[2*p+1][1]) : "r"(bd));
            }
            #pragma unroll
            for (int mt = 0; mt < 4; ++mt)
                #pragma unroll
                for (int nt = 0; nt < 8; ++nt)
                    asm volatile(
                        "mma.sync.aligned.m16n8k16.row.col.f32.f16.f16.f32 "
                        "{%0,%1,%2,%3},{%4,%5,%6,%7},{%8,%9},{%0,%1,%2,%3};\n"
                        : "+f"(acc[mt][nt][0]), "+f"(acc[mt][nt][1]),
                          "+f"(acc[mt][nt][2]), "+f"(acc[mt][nt][3])
                        : "r"(a[mt][0]), "r"(a[mt][1]), "r"(a[mt][2]), "r"(a[mt][3]),
                          "r"(bb[nt][0]), "r"(bb[nt][1]));
        }
    };

    const int ntile = Kdim / BK;
    #pragma unroll
    for (int p = 0; p < STGt - 1; ++p) issue(p, p);
    for (int t = 0; t < ntile; ++t) {
        int rem = ntile - 1 - t;
        if (STGt >= 3 && rem >= 1) asm volatile("cp.async.wait_group 1;\n" ::: "memory");
        else                       asm volatile("cp.async.wait_group 0;\n" ::: "memory");
        __syncthreads();
        compute(t % STGt);
        if (t + STGt - 1 < ntile) issue(t + STGt - 1, (t + STGt - 1) % STGt);
    }

    const int g = lane >> 2, q = lane & 3;

    if (FSTAT) {
        // fp16 C store (real rows only) + masked BN stats from fp32 accs.
        float sum[16], sq[16];
        #pragma unroll
        for (int i = 0; i < 16; ++i) { sum[i] = 0.f; sq[i] = 0.f; }
        #pragma unroll
        for (int mt = 0; mt < 4; ++mt) {
            int rr = wm*64 + mt*16 + g;
            bool ok0 = (rr & 63) < K_;
            bool ok1 = ((rr + 8) & 63) < K_;
            #pragma unroll
            for (int nt = 0; nt < 8; ++nt) {
                int c = n0 + wn*64 + nt*8 + q*2;
                float b0 = bias[c], b1 = bias[c+1];
                float v00 = acc[mt][nt][0] + b0, v01 = acc[mt][nt][1] + b1;
                float v10 = acc[mt][nt][2] + b0, v11 = acc[mt][nt][3] + b1;
                int r = m0 + rr;
                if (ok0) {
                    *(__half2*)&Ch[(size_t)r*ldc + c] = __floats2half2_rn(v00, v01);
                    sum[nt*2]   += v00; sq[nt*2]   += v00*v00;
                    sum[nt*2+1] += v01; sq[nt*2+1] += v01*v01;
                }
                if (ok1) {
                    *(__half2*)&Ch[(size_t)(r+8)*ldc + c] = __floats2half2_rn(v10, v11);
                    sum[nt*2]   += v10; sq[nt*2]   += v10*v10;
                    sum[nt*2+1] += v11; sq[nt*2+1] += v11*v11;
                }
            }
        }
        #pragma unroll
        for (int off = 4; off < 32; off <<= 1) {
            #pragma unroll
            for (int i = 0; i < 16; ++i) {
                sum[i] += __shfl_xor_sync(0xffffffffu, sum[i], off);
                sq[i]  += __shfl_xor_sync(0xffffffffu, sq[i],  off);
            }
        }
        if (lane < 4) {
            #pragma unroll
            for (int nt = 0; nt < 8; ++nt) {
                #pragma unroll
                for (int j = 0; j < 2; ++j) {
                    int c = n0 + wn*64 + nt*8 + lane*2 + j;
                    atomicAdd(&stats[c],      sum[nt*2+j]);
                    atomicAdd(&stats[H_ + c], sq[nt*2+j]);
                }
            }
        }
    } else {
        // 2 batches per CTA; warp row wm owns batch 2*by+wm (rows wm*64..+63).
        float mx[16];
        #pragma unroll
        for (int i = 0; i < 16; ++i) mx[i] = -3.4e38f;
        #pragma unroll
        for (int mt = 0; mt < 4; ++mt) {
            int k0 = mt*16 + g;               // row within batch
            bool ok0 = k0 < K_, ok1 = (k0 + 8) < K_;
            #pragma unroll
            for (int nt = 0; nt < 8; ++nt) {
                int c = n0 + wn*64 + nt*8 + q*2;
                float b0 = bias[c], b1 = bias[c+1];
                if (ok0) { mx[nt*2]   = fmaxf(mx[nt*2],   acc[mt][nt][0] + b0);
                           mx[nt*2+1] = fmaxf(mx[nt*2+1], acc[mt][nt][1] + b1); }
                if (ok1) { mx[nt*2]   = fmaxf(mx[nt*2],   acc[mt][nt][2] + b0);
                           mx[nt*2+1] = fmaxf(mx[nt*2+1], acc[mt][nt][3] + b1); }
            }
        }
        #pragma unroll
        for (int off = 4; off < 32; off <<= 1)
            #pragma unroll
            for (int i = 0; i < 16; ++i)
                mx[i] = fmaxf(mx[i], __shfl_xor_sync(0xffffffffu, mx[i], off));
        if (lane < 4) {
            int b = blockIdx.y*2 + wm;
            #pragma unroll
            for (int nt = 0; nt < 8; ++nt) {
                int c = n0 + wn*64 + nt*8 + lane*2;
                *(float2*)&omax[(size_t)b*E_ + c] = make_float2(mx[nt*2], mx[nt*2+1]);
            }
        }
    }
}

// ---------------- BN apply + ReLU + fp16 into X[:,512:] (real rows only) ------
__global__ void bnapply_kernel(const float* __restrict__ gamma, const float* __restrict__ beta)
{
    int i = blockIdx.x*256 + threadIdx.x;    // 0..M_*H_/2-1
    int row = i >> 8;                        // real row 0..14847
    int cp = (i & 255)*2;
    int b = row / K_;
    int k = row - b*K_;
    size_t r = (size_t)(b*64 + k);
    __half2 x2 = *(const __half2*)&g_hpre[r*H_ + cp];
    const float invM = 1.f / (float)M_;
    float y0, y1;
    {
        float mu  = g_stats[cp] * invM;
        float var = g_stats[H_ + cp] * invM - mu*mu;
        y0 = fmaxf((__low2float(x2) - mu) * rsqrtf(var + 1e-5f) * gamma[cp] + beta[cp], 0.f);
    }
    {
        float mu  = g_stats[cp+1] * invM;
        float var = g_stats[H_ + cp+1] * invM - mu*mu;
        y1 = fmaxf((__high2float(x2) - mu) * rsqrtf(var + 1e-5f) * gamma[cp+1] + beta[cp+1], 0.f);
    }
    *(__half2*)&g_X[r*1024 + 512 + cp] = __floats2half2_rn(y0, y1);
}

// ---------------- launch ------------------------------------------------------
extern "C" void kernel_launch(void* const* d_in, const int* in_sizes, int n_in,
                              void* d_out, int out_size)
{
    const float* emb   = (const float*)d_in[0];
    const float* am    = (const float*)d_in[1];
    const float* Wfc   = (const float*)d_in[2];
    const float* bfc   = (const float*)d_in[3];
    const float* W1    = (const float*)d_in[4];
    const float* b1    = (const float*)d_in[5];
    const float* gamma = (const float*)d_in[6];
    const float* beta  = (const float*)d_in[7];
    const float* W2    = (const float*)d_in[8];
    const float* b2    = (const float*)d_in[9];
    float* out = (float*)d_out;

    void *pX, *pW1h, *pWcat, *pH, *pB2, *pSt;
    cudaGetSymbolAddress(&pX,    g_X);
    cudaGetSymbolAddress(&pW1h,  g_W1h);
    cudaGetSymbolAddress(&pWcat, g_Wcat);
    cudaGetSymbolAddress(&pH,    g_hpre);
    cudaGetSymbolAddress(&pB2,   g_bias2);
    cudaGetSymbolAddress(&pSt,   g_stats);

    const int SMEM1 = 2*STAGE_BYTES;    // 65536  (GEMM1: 3 CTAs/SM)
    const int SMEM2 = 3*STAGE_BYTES;    // 98304  (GEMM2: 2 CTAs/SM, R7-exact)
    cudaFuncSetAttribute((const void*)gemm_tc<true, 2, 3>,
                         cudaFuncAttributeMaxDynamicSharedMemorySize, SMEM1);
    cudaFuncSetAttribute((const void*)gemm_tc<false, 3, 2>,
                         cudaFuncAttributeMaxDynamicSharedMemorySize, SMEM2);

    prep_kernel<<<4096, 256>>>(Wfc, bfc, W1, W2, b2);
    topk_kernel<<<B_, N_>>>(am);
    gather_kernel<<<M_, 128>>>(emb);
    // GEMM1: hpre(fp16) = base @ W1^T + b1, fused BN stats (K=512 -> 8 tiles)
    gemm_tc<true, 2, 3><<<dim3(H_/BN, MP_/BMt), 128, SMEM1>>>(
        (const __half*)pX, 1024, (const __half*)pW1h, D_,
        (__half*)pH, H_, b1, D_, (float*)pSt, nullptr);
    bnapply_kernel<<<(M_*H_/2)/256, 256>>>(gamma, beta);
    // GEMM2: out[b,:] = max_k( X @ [Wfc|W2]^T + (b_fc+b2) ), warp-local max epilogue
    gemm_tc<false, 3, 2><<<dim3(E_/BN, MP_/BMt), 128, SMEM2>>>(
        (const __half*)pX, 1024, (const __half*)pWcat, 1024,
        nullptr, 0, (const float*)pB2, 1024, nullptr, out);
}

// round 12
// speedup vs baseline: 1.1575x; 1.0654x over previous
#include <cuda_runtime.h>
#include <cuda_fp16.h>
#include <cstdint>

#define B_ 256
#define N_ 192
#define D_ 512
#define E_ 1024
#define H_ 512
#define K_ 58
#define M_ (B_*K_)        // 14848 real rows
#define MP_ (B_*64)       // 16384 padded rows (64 per batch, rows k>=58 stay zero)

// ---------------- scratch (static device globals; zero-init, no allocation) --
__device__ __half g_X[(size_t)MP_*1024];    // [MP,1024]: 0:512 base, 512:1024 bn(relu(h)); pad rows 0
__device__ __half g_hpre[(size_t)MP_*H_];   // [MP,512] fp16 pre-BN hidden
__device__ __half g_W1h[H_*D_];             // fp16 W1
__device__ __half g_Wcat[E_*1024];          // fp16 [W_fc | W2]
__device__ float  g_bias2[E_];              // b_fc + b2
__device__ float  g_stats[2*H_];            // col sums / sumsq
__device__ int    g_idx[B_*K_];             // selected patch indices

// ---------------- top-K by rank counting (exact lax.top_k set semantics) -----
__global__ void topk_kernel(const float* __restrict__ am)
{
    __shared__ float sv[N_];
    __shared__ int cnt;
    int b = blockIdx.x, t = threadIdx.x;
    if (t == 0) cnt = 0;
    sv[t] = am[(size_t)b*((N_+1)*(N_+1)) + 1 + t];
    __syncthreads();
    float my = sv[t];
    int r = 0;
    #pragma unroll 8
    for (int i = 0; i < N_; ++i) {
        float v = sv[i];
        r += (v > my) || (v == my && i < t);
    }
    if (r < K_) {
        int p = atomicAdd(&cnt, 1);
        g_idx[b*K_ + p] = t;
    }
}

// ---------------- fused prep + gather (disjoint block ranges, one launch) -----
// blocks [0, M_): gather + L2 norm + fp16 into padded X layout.
// blocks [M_, M_+8192): weight casts + bias fuse + stat zeroing (128 thr each).
__global__ void prep_gather_kernel(const float* __restrict__ emb,
                                   const float* __restrict__ Wfc, const float* __restrict__ bfc,
                                   const float* __restrict__ W1,  const float* __restrict__ W2,
                                   const float* __restrict__ b2)
{
    int bid = blockIdx.x;
    int t = threadIdx.x;
    if (bid < M_) {
        int b   = bid / K_;
        int k   = bid - b*K_;
        int p   = g_idx[bid];
        const float4* src = (const float4*)(emb + (size_t)(b*N_ + p)*D_);
        float4 v = src[t];
        float s = v.x*v.x + v.y*v.y + v.z*v.z + v.w*v.w;
        #pragma unroll
        for (int o = 16; o; o >>= 1) s += __shfl_xor_sync(0xffffffffu, s, o);
        __shared__ float sm[4];
        if ((t & 31) == 0) sm[t >> 5] = s;
        __syncthreads();
        float nrm = sqrtf(sm[0] + sm[1] + sm[2] + sm[3]) + 1e-8f;
        size_t r = (size_t)(b*64 + k);
        __half2* dst = (__half2*)(g_X + r*1024 + t*4);
        dst[0] = __floats2half2_rn(v.x/nrm, v.y/nrm);
        dst[1] = __floats2half2_rn(v.z/nrm, v.w/nrm);
    } else {
        int i = (bid - M_)*128 + t;        // 0..1048575
        {
            int e = i >> 10, c = i & 1023;
            float v = (c < 512) ? Wfc[e*512 + c] : W2[e*512 + (c - 512)];
            g_Wcat[i] = __float2half_rn(v);
        }
        if (i < H_*D_) g_W1h[i] = __float2half_rn(W1[i]);
        if (i < E_)    g_bias2[i] = bfc[i] + b2[i];
        if (i < 2*H_)  g_stats[i] = 0.f;
    }
}

// ---------------- fp16 tensor-core GEMM: C = A @ B^T + bias -------------------
// BM=128, BN=128; 128 threads = 4 warps (2x2), warp tile 64x64.
// Template: BKt (k-chunk), STGt (cp.async ring depth), MINB (min blocks/SM).
// GEMM1: BKt=32, STGt=4, MINB=3 -> 64KB smem, 3 CTAs/SM, 1.15 waves.
// GEMM2: BKt=64, STGt=3, MINB=2 -> 96KB smem, 2 CTAs/SM (R7-exact optimum).
// FSTAT: fp16 C store (real rows only) + masked BN column sums/sumsq.
// !FSTAT: BM=128 = 2 padded batches; warp-local masked max over K -> omax.
#define BMt 128
#define BN 128

__device__ __forceinline__ void cp16(uint32_t dst, const void* src) {
    asm volatile("cp.async.cg.shared.global [%0], [%1], 16;\n" :: "r"(dst), "l"(src));
}
__device__ __forceinline__ uint32_t smem_u32(const void* p) {
    uint32_t a;
    asm("{ .reg .u64 t; cvta.to.shared.u64 t, %1; cvt.u32.u64 %0, t; }" : "=r"(a) : "l"(p));
    return a;
}

template<bool FSTAT, int BKt, int STGt, int MINB>
__global__ __launch_bounds__(128, MINB)
void gemm_tc(const __half* __restrict__ A, int lda,
             const __half* __restrict__ Bm, int ldb,
             __half* __restrict__ Ch, int ldc,
             const float* __restrict__ bias, int Kdim,
             float* __restrict__ stats, float* __restrict__ omax)
{
    constexpr int STAGE_BYTES = (BMt + BN)*BKt*2;
    constexpr int A_BYTES     = BMt*BKt*2;
    constexpr int ROWB        = BKt*2;          // bytes per smem row
    constexpr int CPR         = BKt/8;          // 16B chunks per row
    constexpr int RSTEP       = 128/CPR;        // rows per cooperative pass
    constexpr int KS          = BKt/16;         // k16 steps per tile

    extern __shared__ __half sh[];
    const int tid  = threadIdx.x;
    const int lane = tid & 31, wid = tid >> 5;
    const int wm = wid >> 1, wn = wid & 1;      // 2x2 warp grid, tile 64x64
    const int m0 = blockIdx.y*BMt, n0 = blockIdx.x*BN;

    uint32_t sbase = smem_u32(sh);

    // swizzle: BK64 rows (8 chunks): c ^ (r&7); BK32 rows (4 chunks): c ^ ((r>>1)&3)
    auto swz = [](int c, int r) -> int {
        return (BKt == 64) ? (c ^ (r & 7)) : (c ^ ((r >> 1) & 3));
    };

    float acc[4][8][4];
    #pragma unroll
    for (int i = 0; i < 4; ++i)
        #pragma unroll
        for (int j = 0; j < 8; ++j)
            #pragma unroll
            for (int k = 0; k < 4; ++k) acc[i][j][k] = 0.f;

    // global->smem cooperative copy descriptors
    const int cr = tid / CPR;
    const int cc = tid % CPR;
    const __half* Ag[CPR]; uint32_t oA[CPR];
    #pragma unroll
    for (int i = 0; i < CPR; ++i) {
        int r = cr + i*RSTEP;
        Ag[i] = A + (size_t)(m0 + r)*lda + cc*8;
        oA[i] = r*ROWB + swz(cc, r)*16;
    }
    const __half* Bg[CPR]; uint32_t oB[CPR];
    #pragma unroll
    for (int i = 0; i < CPR; ++i) {
        int r = cr + i*RSTEP;
        Bg[i] = Bm + (size_t)(n0 + r)*ldb + cc*8;
        oB[i] = A_BYTES + r*ROWB + swz(cc, r)*16;
    }

    // ldmatrix per-lane descriptors
    const int mi  = lane >> 3;
    const int lr8 = lane & 7;
    int arow[4];
    #pragma unroll
    for (int mt = 0; mt < 4; ++mt) arow[mt] = wm*64 + mt*16 + ((mi & 1) << 3) + lr8;
    const int akadd = mi >> 1;
    int brow[4];
    #pragma unroll
    for (int p = 0; p < 4; ++p) brow[p] = wn*64 + ((2*p + (mi >> 1)) << 3) + lr8;
    const int bkadd = mi & 1;

    auto issue = [&](int kt, int st) {
        uint32_t so = sbase + st*STAGE_BYTES;
        int ko = kt*BKt;
        #pragma unroll
        for (int i = 0; i < CPR; ++i) cp16(so + oA[i], Ag[i] + ko);
        #pragma unroll
        for (int i = 0; i < CPR; ++i) cp16(so + oB[i], Bg[i] + ko);
        asm volatile("cp.async.commit_group;\n");
    };

    auto compute = [&](int st) {
        uint32_t abase = sbase + st*STAGE_BYTES;
        uint32_t bbase = abase + A_BYTES;
        #pragma unroll
        for (int ks = 0; ks < KS; ++ks) {
            uint32_t a[4][4], bb[8][2];
            #pragma unroll
            for (int mt = 0; mt < 4; ++mt) {
                int rr = arow[mt];
                uint32_t ad = abase + rr*ROWB + swz(2*ks + akadd, rr)*16;
                asm volatile("ldmatrix.sync.aligned.m8n8.x4.shared.b16 {%0,%1,%2,%3},[%4];"
                    : "=r"(a[mt][0]), "=r"(a[mt][1]), "=r"(a[mt][2]), "=r"(a[mt][3]) : "r"(ad));
            }
            #pragma unroll
            for (int p = 0; p < 4; ++p) {
                int rr = brow[p];
                uint32_t bd = bbase + rr*ROWB + swz(2*ks + bkadd, rr)*16;
                asm volatile("ldmatrix.sync.aligned.m8n8.x4.shared.b16 {%0,%1,%2,%3},[%4];"
                    : "=r"(bb[2*p][0]), "=r"(bb[2*p][1]),
                      "=r"(bb[2*p+1][0]), "=r"(bb[2*p+1][1]) : "r"(bd));
            }
            #pragma unroll
            for (int mt = 0; mt < 4; ++mt)
                #pragma unroll
                for (int nt = 0; nt < 8; ++nt)
                    asm volatile(
                        "mma.sync.aligned.m16n8k16.row.col.f32.f16.f16.f32 "
                        "{%0,%1,%2,%3},{%4,%5,%6,%7},{%8,%9},{%0,%1,%2,%3};\n"
                        : "+f"(acc[mt][nt][0]), "+f"(acc[mt][nt][1]),
                          "+f"(acc[mt][nt][2]), "+f"(acc[mt][nt][3])
                        : "r"(a[mt][0]), "r"(a[mt][1]), "r"(a[mt][2]), "r"(a[mt][3]),
                          "r"(bb[nt][0]), "r"(bb[nt][1]));
        }
    };

    const int ntile = Kdim / BKt;
    #pragma unroll
    for (int p = 0; p < STGt - 1; ++p) issue(p, p);
    for (int t = 0; t < ntile; ++t) {
        int rem = ntile - 1 - t;
        if      (STGt >= 4 && rem >= 2) asm volatile("cp.async.wait_group 2;\n" ::: "memory");
        else if (STGt >= 3 && rem >= 1) asm volatile("cp.async.wait_group 1;\n" ::: "memory");
        else                            asm volatile("cp.async.wait_group 0;\n" ::: "memory");
        __syncthreads();
        compute(t % STGt);
        if (t + STGt - 1 < ntile) issue(t + STGt - 1, (t + STGt - 1) % STGt);
    }

    const int g = lane >> 2, q = lane & 3;

    if (FSTAT) {
        // fp16 C store (real rows only) + masked BN stats from fp32 accs.
        float sum[16], sq[16];
        #pragma unroll
        for (int i = 0; i < 16; ++i) { sum[i] = 0.f; sq[i] = 0.f; }
        #pragma unroll
        for (int mt = 0; mt < 4; ++mt) {
            int rr = wm*64 + mt*16 + g;
            bool ok0 = (rr & 63) < K_;
            bool ok1 = ((rr + 8) & 63) < K_;
            #pragma unroll
            for (int nt = 0; nt < 8; ++nt) {
                int c = n0 + wn*64 + nt*8 + q*2;
                float b0 = bias[c], b1 = bias[c+1];
                float v00 = acc[mt][nt][0] + b0, v01 = acc[mt][nt][1] + b1;
                float v10 = acc[mt][nt][2] + b0, v11 = acc[mt][nt][3] + b1;
                int r = m0 + rr;
                if (ok0) {
                    *(__half2*)&Ch[(size_t)r*ldc + c] = __floats2half2_rn(v00, v01);
                    sum[nt*2]   += v00; sq[nt*2]   += v00*v00;
                    sum[nt*2+1] += v01; sq[nt*2+1] += v01*v01;
                }
                if (ok1) {
                    *(__half2*)&Ch[(size_t)(r+8)*ldc + c] = __floats2half2_rn(v10, v11);
                    sum[nt*2]   += v10; sq[nt*2]   += v10*v10;
                    sum[nt*2+1] += v11; sq[nt*2+1] += v11*v11;
                }
            }
        }
        #pragma unroll
        for (int off = 4; off < 32; off <<= 1) {
            #pragma unroll
            for (int i = 0; i < 16; ++i) {
                sum[i] += __shfl_xor_sync(0xffffffffu, sum[i], off);
                sq[i]  += __shfl_xor_sync(0xffffffffu, sq[i],  off);
            }
        }
        if (lane < 4) {
            #pragma unroll
            for (int nt = 0; nt < 8; ++nt) {
                #pragma unroll
                for (int j = 0; j < 2; ++j) {
                    int c = n0 + wn*64 + nt*8 + lane*2 + j;
                    atomicAdd(&stats[c],      sum[nt*2+j]);
                    atomicAdd(&stats[H_ + c], sq[nt*2+j]);
                }
            }
        }
    } else {
        // 2 batches per CTA; warp row wm owns batch 2*by+wm (rows wm*64..+63).
        float mx[16];
        #pragma unroll
        for (int i = 0; i < 16; ++i) mx[i] = -3.4e38f;
        #pragma unroll
        for (int mt = 0; mt < 4; ++mt) {
            int k0 = mt*16 + g;               // row within batch
            bool ok0 = k0 < K_, ok1 = (k0 + 8) < K_;
            #pragma unroll
            for (int nt = 0; nt < 8; ++nt) {
                int c = n0 + wn*64 + nt*8 + q*2;
                float b0 = bias[c], b1 = bias[c+1];
                if (ok0) { mx[nt*2]   = fmaxf(mx[nt*2],   acc[mt][nt][0] + b0);
                           mx[nt*2+1] = fmaxf(mx[nt*2+1], acc[mt][nt][1] + b1); }
                if (ok1) { mx[nt*2]   = fmaxf(mx[nt*2],   acc[mt][nt][2] + b0);
                           mx[nt*2+1] = fmaxf(mx[nt*2+1], acc[mt][nt][3] + b1); }
            }
        }
        #pragma unroll
        for (int off = 4; off < 32; off <<= 1)
            #pragma unroll
            for (int i = 0; i < 16; ++i)
                mx[i] = fmaxf(mx[i], __shfl_xor_sync(0xffffffffu, mx[i], off));
        if (lane < 4) {
            int b = blockIdx.y*2 + wm;
            #pragma unroll
            for (int nt = 0; nt < 8; ++nt) {
                int c = n0 + wn*64 + nt*8 + lane*2;
                *(float2*)&omax[(size_t)b*E_ + c] = make_float2(mx[nt*2], mx[nt*2+1]);
            }
        }
    }
}

// ---------------- BN apply + ReLU + fp16 into X[:,512:] (real rows only) ------
__global__ void bnapply_kernel(const float* __restrict__ gamma, const float* __restrict__ beta)
{
    int i = blockIdx.x*256 + threadIdx.x;    // 0..M_*H_/2-1
    int row = i >> 8;                        // real row 0..14847
    int cp = (i & 255)*2;
    int b = row / K_;
    int k = row - b*K_;
    size_t r = (size_t)(b*64 + k);
    __half2 x2 = *(const __half2*)&g_hpre[r*H_ + cp];
    const float invM = 1.f / (float)M_;
    float y0, y1;
    {
        float mu  = g_stats[cp] * invM;
        float var = g_stats[H_ + cp] * invM - mu*mu;
        y0 = fmaxf((__low2float(x2) - mu) * rsqrtf(var + 1e-5f) * gamma[cp] + beta[cp], 0.f);
    }
    {
        float mu  = g_stats[cp+1] * invM;
        float var = g_stats[H_ + cp+1] * invM - mu*mu;
        y1 = fmaxf((__high2float(x2) - mu) * rsqrtf(var + 1e-5f) * gamma[cp+1] + beta[cp+1], 0.f);
    }
    *(__half2*)&g_X[r*1024 + 512 + cp] = __floats2half2_rn(y0, y1);
}

// ---------------- launch ------------------------------------------------------
extern "C" void kernel_launch(void* const* d_in, const int* in_sizes, int n_in,
                              void* d_out, int out_size)
{
    const float* emb   = (const float*)d_in[0];
    const float* am    = (const float*)d_in[1];
    const float* Wfc   = (const float*)d_in[2];
    const float* bfc   = (const float*)d_in[3];
    const float* W1    = (const float*)d_in[4];
    const float* b1    = (const float*)d_in[5];
    const float* gamma = (const float*)d_in[6];
    const float* beta  = (const float*)d_in[7];
    const float* W2    = (const float*)d_in[8];
    const float* b2    = (const float*)d_in[9];
    float* out = (float*)d_out;

    void *pX, *pW1h, *pWcat, *pH, *pB2, *pSt;
    cudaGetSymbolAddress(&pX,    g_X);
    cudaGetSymbolAddress(&pW1h,  g_W1h);
    cudaGetSymbolAddress(&pWcat, g_Wcat);
    cudaGetSymbolAddress(&pH,    g_hpre);
    cudaGetSymbolAddress(&pB2,   g_bias2);
    cudaGetSymbolAddress(&pSt,   g_stats);

    const int SMEM1 = 4*(BMt + BN)*32*2;   // 65536  (BK=32, 4-stage, 3 CTAs/SM)
    const int SMEM2 = 3*(BMt + BN)*64*2;   // 98304  (BK=64, 3-stage, 2 CTAs/SM)
    cudaFuncSetAttribute((const void*)gemm_tc<true, 32, 4, 3>,
                         cudaFuncAttributeMaxDynamicSharedMemorySize, SMEM1);
    cudaFuncSetAttribute((const void*)gemm_tc<false, 64, 3, 2>,
                         cudaFuncAttributeMaxDynamicSharedMemorySize, SMEM2);

    topk_kernel<<<B_, N_>>>(am);
    // fused: gather (blocks 0..M_-1) + weight prep (blocks M_..M_+8191)
    prep_gather_kernel<<<M_ + 8192, 128>>>(emb, Wfc, bfc, W1, W2, b2);
    // GEMM1: hpre(fp16) = base @ W1^T + b1, fused BN stats (K=512 -> 16 tiles)
    gemm_tc<true, 32, 4, 3><<<dim3(H_/BN, MP_/BMt), 128, SMEM1>>>(
        (const __half*)pX, 1024, (const __half*)pW1h, D_,
        (__half*)pH, H_, b1, D_, (float*)pSt, nullptr);
    bnapply_kernel<<<(M_*H_/2)/256, 256>>>(gamma, beta);
    // GEMM2: out[b,:] = max_k( X @ [Wfc|W2]^T + (b_fc+b2) ), warp-local max epilogue
    gemm_tc<false, 64, 3, 2><<<dim3(E_/BN, MP_/BMt), 128, SMEM2>>>(
        (const __half*)pX, 1024, (const __half*)pWcat, 1024,
        nullptr, 0, (const float*)pB2, 1024, nullptr, out);
}

// round 14
// speedup vs baseline: 1.1616x; 1.0036x over previous
#include <cuda_runtime.h>
#include <cuda_fp16.h>
#include <cstdint>

#define B_ 256
#define N_ 192
#define D_ 512
#define E_ 1024
#define H_ 512
#define K_ 58
#define M_ (B_*K_)        // 14848 real rows
#define MP_ (B_*64)       // 16384 padded rows (64 per batch, rows k>=58 stay zero)

// ---------------- scratch (static device globals; zero-init, no allocation) --
__device__ __half g_X[(size_t)MP_*1024];    // [MP,1024]: 0:512 base, 512:1024 bn(relu(h)); pad rows 0
__device__ __half g_hpre[(size_t)MP_*H_];   // [MP,512] fp16 pre-BN hidden
__device__ __half g_W1h[H_*D_];             // fp16 W1
__device__ __half g_Wcat[E_*1024];          // fp16 [W_fc | W2]
__device__ float  g_bias2[E_];              // b_fc + b2
__device__ float  g_stats[2*H_];            // col sums / sumsq
__device__ float  g_bnsc[H_];               // BN scale  = rsqrt(var+eps)*gamma
__device__ float  g_bnsh[H_];               // BN shift  = beta - mu*scale
__device__ int    g_idx[B_*K_];             // selected patch indices

// ---------------- top-K by rank counting (exact lax.top_k set semantics) -----
__global__ void topk_kernel(const float* __restrict__ am)
{
    __shared__ float sv[N_];
    __shared__ int cnt;
    int b = blockIdx.x, t = threadIdx.x;
    if (t == 0) cnt = 0;
    sv[t] = am[(size_t)b*((N_+1)*(N_+1)) + 1 + t];
    __syncthreads();
    float my = sv[t];
    int r = 0;
    #pragma unroll 8
    for (int i = 0; i < N_; ++i) {
        float v = sv[i];
        r += (v > my) || (v == my && i < t);
    }
    if (r < K_) {
        int p = atomicAdd(&cnt, 1);
        g_idx[b*K_ + p] = t;
    }
}

// ---------------- fused prep + gather (disjoint block ranges, one launch) -----
__global__ void prep_gather_kernel(const float* __restrict__ emb,
                                   const float* __restrict__ Wfc, const float* __restrict__ bfc,
                                   const float* __restrict__ W1,  const float* __restrict__ W2,
                                   const float* __restrict__ b2)
{
    int bid = blockIdx.x;
    int t = threadIdx.x;
    if (bid < M_) {
        int b   = bid / K_;
        int k   = bid - b*K_;
        int p   = g_idx[bid];
        const float4* src = (const float4*)(emb + (size_t)(b*N_ + p)*D_);
        float4 v = src[t];
        float s = v.x*v.x + v.y*v.y + v.z*v.z + v.w*v.w;
        #pragma unroll
        for (int o = 16; o; o >>= 1) s += __shfl_xor_sync(0xffffffffu, s, o);
        __shared__ float sm[4];
        if ((t & 31) == 0) sm[t >> 5] = s;
        __syncthreads();
        float nrm = sqrtf(sm[0] + sm[1] + sm[2] + sm[3]) + 1e-8f;
        size_t r = (size_t)(b*64 + k);
        __half2* dst = (__half2*)(g_X + r*1024 + t*4);
        dst[0] = __floats2half2_rn(v.x/nrm, v.y/nrm);
        dst[1] = __floats2half2_rn(v.z/nrm, v.w/nrm);
    } else {
        int i = (bid - M_)*128 + t;        // 0..1048575
        {
            int e = i >> 10, c = i & 1023;
            float v = (c < 512) ? Wfc[e*512 + c] : W2[e*512 + (c - 512)];
            g_Wcat[i] = __float2half_rn(v);
        }
        if (i < H_*D_) g_W1h[i] = __float2half_rn(W1[i]);
        if (i < E_)    g_bias2[i] = bfc[i] + b2[i];
        if (i < 2*H_)  g_stats[i] = 0.f;
    }
}

// ---------------- fp16 tensor-core GEMM: C = A @ B^T + bias -------------------
// BM=128, BN=128; 128 threads = 4 warps (2x2), warp tile 64x64.
// GEMM1: BKt=32, STGt=4, MINB=3 -> 64KB smem, 3 CTAs/SM.
// GEMM2: BKt=64, STGt=3, MINB=2 -> 96KB smem, 2 CTAs/SM (R7 optimum).
#define BMt 128
#define BN 128

__device__ __forceinline__ void cp16(uint32_t dst, const void* src) {
    asm volatile("cp.async.cg.shared.global [%0], [%1], 16;\n" :: "r"(dst), "l"(src));
}
__device__ __forceinline__ uint32_t smem_u32(const void* p) {
    uint32_t a;
    asm("{ .reg .u64 t; cvta.to.shared.u64 t, %1; cvt.u32.u64 %0, t; }" : "=r"(a) : "l"(p));
    return a;
}

template<bool FSTAT, int BKt, int STGt, int MINB>
__global__ __launch_bounds__(128, MINB)
void gemm_tc(const __half* __restrict__ A, int lda,
             const __half* __restrict__ Bm, int ldb,
             __half* __restrict__ Ch, int ldc,
             const float* __restrict__ bias, int Kdim,
             float* __restrict__ stats, float* __restrict__ omax)
{
    constexpr int STAGE_BYTES = (BMt + BN)*BKt*2;
    constexpr int A_BYTES     = BMt*BKt*2;
    constexpr int ROWB        = BKt*2;
    constexpr int CPR         = BKt/8;
    constexpr int RSTEP       = 128/CPR;
    constexpr int KS          = BKt/16;

    extern __shared__ __half sh[];
    const int tid  = threadIdx.x;
    const int lane = tid & 31, wid = tid >> 5;
    const int wm = wid >> 1, wn = wid & 1;
    const int m0 = blockIdx.y*BMt, n0 = blockIdx.x*BN;

    uint32_t sbase = smem_u32(sh);

    auto swz = [](int c, int r) -> int {
        return (BKt == 64) ? (c ^ (r & 7)) : (c ^ ((r >> 1) & 3));
    };

    float acc[4][8][4];
    #pragma unroll
    for (int i = 0; i < 4; ++i)
        #pragma unroll
        for (int j = 0; j < 8; ++j)
            #pragma unroll
            for (int k = 0; k < 4; ++k) acc[i][j][k] = 0.f;

    const int cr = tid / CPR;
    const int cc = tid % CPR;
    const __half* Ag[CPR]; uint32_t oA[CPR];
    #pragma unroll
    for (int i = 0; i < CPR; ++i) {
        int r = cr + i*RSTEP;
        Ag[i] = A + (size_t)(m0 + r)*lda + cc*8;
        oA[i] = r*ROWB + swz(cc, r)*16;
    }
    const __half* Bg[CPR]; uint32_t oB[CPR];
    #pragma unroll
    for (int i = 0; i < CPR; ++i) {
        int r = cr + i*RSTEP;
        Bg[i] = Bm + (size_t)(n0 + r)*ldb + cc*8;
        oB[i] = A_BYTES + r*ROWB + swz(cc, r)*16;
    }

    const int mi  = lane >> 3;
    const int lr8 = lane & 7;
    int arow[4];
    #pragma unroll
    for (int mt = 0; mt < 4; ++mt) arow[mt] = wm*64 + mt*16 + ((mi & 1) << 3) + lr8;
    const int akadd = mi >> 1;
    int brow[4];
    #pragma unroll
    for (int p = 0; p < 4; ++p) brow[p] = wn*64 + ((2*p + (mi >> 1)) << 3) + lr8;
    const int bkadd = mi & 1;

    auto issue = [&](int kt, int st) {
        uint32_t so = sbase + st*STAGE_BYTES;
        int ko = kt*BKt;
        #pragma unroll
        for (int i = 0; i < CPR; ++i) cp16(so + oA[i], Ag[i] + ko);
        #pragma unroll
        for (int i = 0; i < CPR; ++i) cp16(so + oB[i], Bg[i] + ko);
        asm volatile("cp.async.commit_group;\n");
    };

    auto compute = [&](int st) {
        uint32_t abase = sbase + st*STAGE_BYTES;
        uint32_t bbase = abase + A_BYTES;
        #pragma unroll
        for (int ks = 0; ks < KS; ++ks) {
            uint32_t a[4][4], bb[8][2];
            #pragma unroll
            for (int mt = 0; mt < 4; ++mt) {
                int rr = arow[mt];
                uint32_t ad = abase + rr*ROWB + swz(2*ks + akadd, rr)*16;
                asm volatile("ldmatrix.sync.aligned.m8n8.x4.shared.b16 {%0,%1,%2,%3},[%4];"
                    : "=r"(a[mt][0]), "=r"(a[mt][1]), "=r"(a[mt][2]), "=r"(a[mt][3]) : "r"(ad));
            }
            #pragma unroll
            for (int p = 0; p < 4; ++p) {
                int rr = brow[p];
                uint32_t bd = bbase + rr*ROWB + swz(2*ks + bkadd, rr)*16;
                asm volatile("ldmatrix.sync.aligned.m8n8.x4.shared.b16 {%0,%1,%2,%3},[%4];"
                    : "=r"(bb[2*p][0]), "=r"(bb[2*p][1]),
                      "=r"(bb[2*p+1][0]), "=r"(bb[2*p+1][1]) : "r"(bd));
            }
            #pragma unroll
            for (int mt = 0; mt < 4; ++mt)
                #pragma unroll
                for (int nt = 0; nt < 8; ++nt)
                    asm volatile(
                        "mma.sync.aligned.m16n8k16.row.col.f32.f16.f16.f32 "
                        "{%0,%1,%2,%3},{%4,%5,%6,%7},{%8,%9},{%0,%1,%2,%3};\n"
                        : "+f"(acc[mt][nt][0]), "+f"(acc[mt][nt][1]),
                          "+f"(acc[mt][nt][2]), "+f"(acc[mt][nt][3])
                        : "r"(a[mt][0]), "r"(a[mt][1]), "r"(a[mt][2]), "r"(a[mt][3]),
                          "r"(bb[nt][0]), "r"(bb[nt][1]));
        }
    };

    const int ntile = Kdim / BKt;
    #pragma unroll
    for (int p = 0; p < STGt - 1; ++p) issue(p, p);
    for (int t = 0; t < ntile; ++t) {
        int rem = ntile - 1 - t;
        if      (STGt >= 4 && rem >= 2) asm volatile("cp.async.wait_group 2;\n" ::: "memory");
        else if (STGt >= 3 && rem >= 1) asm volatile("cp.async.wait_group 1;\n" ::: "memory");
        else                            asm volatile("cp.async.wait_group 0;\n" ::: "memory");
        __syncthreads();
        compute(t % STGt);
        if (t + STGt - 1 < ntile) issue(t + STGt - 1, (t + STGt - 1) % STGt);
    }

    const int g = lane >> 2, q = lane & 3;

    if (FSTAT) {
        float sum[16], sq[16];
        #pragma unroll
        for (int i = 0; i < 16; ++i) { sum[i] = 0.f; sq[i] = 0.f; }
        #pragma unroll
        for (int mt = 0; mt < 4; ++mt) {
            int rr = wm*64 + mt*16 + g;
            bool ok0 = (rr & 63) < K_;
            bool ok1 = ((rr + 8) & 63) < K_;
            #pragma unroll
            for (int nt = 0; nt < 8; ++nt) {
                int c = n0 + wn*64 + nt*8 + q*2;
                float b0 = bias[c], b1 = bias[c+1];
                float v00 = acc[mt][nt][0] + b0, v01 = acc[mt][nt][1] + b1;
                float v10 = acc[mt][nt][2] + b0, v11 = acc[mt][nt][3] + b1;
                int r = m0 + rr;
                if (ok0) {
                    *(__half2*)&Ch[(size_t)r*ldc + c] = __floats2half2_rn(v00, v01);
                    sum[nt*2]   += v00; sq[nt*2]   += v00*v00;
                    sum[nt*2+1] += v01; sq[nt*2+1] += v01*v01;
                }
                if (ok1) {
                    *(__half2*)&Ch[(size_t)(r+8)*ldc + c] = __floats2half2_rn(v10, v11);
                    sum[nt*2]   += v10; sq[nt*2]   += v10*v10;
                    sum[nt*2+1] += v11; sq[nt*2+1] += v11*v11;
                }
            }
        }
        #pragma unroll
        for (int off = 4; off < 32; off <<= 1) {
            #pragma unroll
            for (int i = 0; i < 16; ++i) {
                sum[i] += __shfl_xor_sync(0xffffffffu, sum[i], off);
                sq[i]  += __shfl_xor_sync(0xffffffffu, sq[i],  off);
            }
        }
        if (lane < 4) {
            #pragma unroll
            for (int nt = 0; nt < 8; ++nt) {
                #pragma unroll
                for (int j = 0; j < 2; ++j) {
                    int c = n0 + wn*64 + nt*8 + lane*2 + j;
                    atomicAdd(&stats[c],      sum[nt*2+j]);
                    atomicAdd(&stats[H_ + c], sq[nt*2+j]);
                }
            }
        }
    } else {
        float mx[16];
        #pragma unroll
        for (int i = 0; i < 16; ++i) mx[i] = -3.4e38f;
        #pragma unroll
        for (int mt = 0; mt < 4; ++mt) {
            int k0 = mt*16 + g;
            bool ok0 = k0 < K_, ok1 = (k0 + 8) < K_;
            #pragma unroll
            for (int nt = 0; nt < 8; ++nt) {
                int c = n0 + wn*64 + nt*8 + q*2;
                float b0 = bias[c], b1 = bias[c+1];
                if (ok0) { mx[nt*2]   = fmaxf(mx[nt*2],   acc[mt][nt][0] + b0);
                           mx[nt*2+1] = fmaxf(mx[nt*2+1], acc[mt][nt][1] + b1); }
                if (ok1) { mx[nt*2]   = fmaxf(mx[nt*2],   acc[mt][nt][2] + b0);
                           mx[nt*2+1] = fmaxf(mx[nt*2+1], acc[mt][nt][3] + b1); }
            }
        }
        #pragma unroll
        for (int off = 4; off < 32; off <<= 1)
            #pragma unroll
            for (int i = 0; i < 16; ++i)
                mx[i] = fmaxf(mx[i], __shfl_xor_sync(0xffffffffu, mx[i], off));
        if (lane < 4) {
            int b = blockIdx.y*2 + wm;
            #pragma unroll
            for (int nt = 0; nt < 8; ++nt) {
                int c = n0 + wn*64 + nt*8 + lane*2;
                *(float2*)&omax[(size_t)b*E_ + c] = make_float2(mx[nt*2], mx[nt*2+1]);
            }
        }
    }
}

// ---------------- BN param precompute (scale/shift per column) -----------------
__global__ void bnparam_kernel(const float* __restrict__ gamma, const float* __restrict__ beta)
{
    int c = threadIdx.x;                  // 512 threads
    const float invM = 1.f / (float)M_;
    float mu  = g_stats[c] * invM;
    float var = g_stats[H_ + c] * invM - mu*mu;
    float sc  = rsqrtf(var + 1e-5f) * gamma[c];
    g_bnsc[c] = sc;
    g_bnsh[c] = beta[c] - mu*sc;
}

// ---------------- BN apply + ReLU + fp16 into X[:,512:] (pure streaming) ------
// One uint4 (8 halfs) per thread; scale/shift from L1-hot 4KB tables.
__global__ void bnapply_kernel()
{
    int i = blockIdx.x*256 + threadIdx.x;    // 0 .. M_*H_/8 - 1
    int row = i >> 6;                        // real row (64 threads/row)
    int c8  = (i & 63)*8;                    // col start (multiple of 8)
    int b = row / K_;
    int k = row - b*K_;
    size_t r = (size_t)(b*64 + k);
    uint4 xv = *(const uint4*)&g_hpre[r*H_ + c8];
    float4 sc0 = *(const float4*)&g_bnsc[c8];
    float4 sc1 = *(const float4*)&g_bnsc[c8 + 4];
    float4 sh0 = *(const float4*)&g_bnsh[c8];
    float4 sh1 = *(const float4*)&g_bnsh[c8 + 4];
    const __half2* xh = (const __half2*)&xv;
    __half2 yv[4];
    {
        float2 x = __half22float2(xh[0]);
        yv[0] = __floats2half2_rn(fmaxf(x.x*sc0.x + sh0.x, 0.f), fmaxf(x.y*sc0.y + sh0.y, 0.f));
    }
    {
        float2 x = __half22float2(xh[1]);
        yv[1] = __floats2half2_rn(fmaxf(x.x*sc0.z + sh0.z, 0.f), fmaxf(x.y*sc0.w + sh0.w, 0.f));
    }
    {
        float2 x = __half22float2(xh[2]);
        yv[2] = __floats2half2_rn(fmaxf(x.x*sc1.x + sh1.x, 0.f), fmaxf(x.y*sc1.y + sh1.y, 0.f));
    }
    {
        float2 x = __half22float2(xh[3]);
        yv[3] = __floats2half2_rn(fmaxf(x.x*sc1.z + sh1.z, 0.f), fmaxf(x.y*sc1.w + sh1.w, 0.f));
    }
    *(uint4*)&g_X[r*1024 + 512 + c8] = *(const uint4*)yv;
}

// ---------------- launch ------------------------------------------------------
extern "C" void kernel_launch(void* const* d_in, const int* in_sizes, int n_in,
                              void* d_out, int out_size)
{
    const float* emb   = (const float*)d_in[0];
    const float* am    = (const float*)d_in[1];
    const float* Wfc   = (const float*)d_in[2];
    const float* bfc   = (const float*)d_in[3];
    const float* W1    = (const float*)d_in[4];
    const float* b1    = (const float*)d_in[5];
    const float* gamma = (const float*)d_in[6];
    const float* beta  = (const float*)d_in[7];
    const float* W2    = (const float*)d_in[8];
    const float* b2    = (const float*)d_in[9];
    float* out = (float*)d_out;

    void *pX, *pW1h, *pWcat, *pH, *pB2, *pSt;
    cudaGetSymbolAddress(&pX,    g_X);
    cudaGetSymbolAddress(&pW1h,  g_W1h);
    cudaGetSymbolAddress(&pWcat, g_Wcat);
    cudaGetSymbolAddress(&pH,    g_hpre);
    cudaGetSymbolAddress(&pB2,   g_bias2);
    cudaGetSymbolAddress(&pSt,   g_stats);

    const int SMEM1 = 4*(BMt + BN)*32*2;   // 65536  (BK=32, 4-stage, 3 CTAs/SM)
    const int SMEM2 = 3*(BMt + BN)*64*2;   // 98304  (BK=64, 3-stage, 2 CTAs/SM)
    cudaFuncSetAttribute((const void*)gemm_tc<true, 32, 4, 3>,
                         cudaFuncAttributeMaxDynamicSharedMemorySize, SMEM1);
    cudaFuncSetAttribute((const void*)gemm_tc<false, 64, 3, 2>,
                         cudaFuncAttributeMaxDynamicSharedMemorySize, SMEM2);

    topk_kernel<<<B_, N_>>>(am);
    prep_gather_kernel<<<M_ + 8192, 128>>>(emb, Wfc, bfc, W1, W2, b2);
    // GEMM1: hpre(fp16) = base @ W1^T + b1, fused BN stats
    gemm_tc<true, 32, 4, 3><<<dim3(H_/BN, MP_/BMt), 128, SMEM1>>>(
        (const __half*)pX, 1024, (const __half*)pW1h, D_,
        (__half*)pH, H_, b1, D_, (float*)pSt, nullptr);
    bnparam_kernel<<<1, H_>>>(gamma, beta);
    bnapply_kernel<<<(M_*H_/8)/256, 256>>>();
    // GEMM2: out[b,:] = max_k( X @ [Wfc|W2]^T + (b_fc+b2) )
    gemm_tc<false, 64, 3, 2><<<dim3(E_/BN, MP_/BMt), 128, SMEM2>>>(
        (const __half*)pX, 1024, (const __half*)pWcat, 1024,
        nullptr, 0, (const float*)pB2, 1024, nullptr, out);
}